// round 2
// baseline (speedup 1.0000x reference)
#include <cuda_runtime.h>
#include <cuda_bf16.h>

#define BATCH 4096
#define TT    1024
#define NVOC  32000
#define HID   16

// Scratch (device globals: allocation-free rule)
__device__ float g_xtab[NVOC * HID];   // 2MB: precomputed x-projection per token
__device__ float g_hfin[BATCH * HID];  // 256KB: final hidden states

// Packed fp32x2 FMA (FFMA2) — 2x FP32 FMA throughput, PTX-only path
__device__ __forceinline__ float2 ffma2(float2 a, float2 b, float2 c) {
    float2 d;
    asm("{\n\t"
        ".reg .b64 ra, rb, rc;\n\t"
        "mov.b64 ra, {%2, %3};\n\t"
        "mov.b64 rb, {%4, %5};\n\t"
        "mov.b64 rc, {%6, %7};\n\t"
        "fma.rn.f32x2 rc, ra, rb, rc;\n\t"
        "mov.b64 {%0, %1}, rc;\n\t"
        "}"
        : "=f"(d.x), "=f"(d.y)
        : "f"(a.x), "f"(a.y), "f"(b.x), "f"(b.y), "f"(c.x), "f"(c.y));
    return d;
}

// Accurate-enough tanh: 1 - 2/(exp2(2*log2e*x)+1). ~1e-6 rel err (ex2/rcp approx
// are 2^-22-accurate), saturates correctly at +-inf. 2 MUFU + 3 ALU.
__device__ __forceinline__ float tanh_fast(float x) {
    float e, r;
    float a = x * 2.8853900817779268f;   // 2*log2(e)
    asm("ex2.approx.f32 %0, %1;" : "=f"(e) : "f"(a));
    asm("rcp.approx.f32 %0, %1;" : "=f"(r) : "f"(e + 1.0f));
    return fmaf(-2.0f, r, 1.0f);
}

// ---------------------------------------------------------------------------
// Kernel 1: xtab[v][o] = Wx_b[o] + sum_h embed[v][h] * Wx_w[o][h]
// ---------------------------------------------------------------------------
__global__ void build_xtab(const float* __restrict__ embed,
                           const float* __restrict__ Wxw,
                           const float* __restrict__ Wxb) {
    int tid = blockIdx.x * blockDim.x + threadIdx.x;
    if (tid >= NVOC * HID) return;
    int v = tid >> 4;
    int o = tid & 15;
    const float4* er = (const float4*)(embed + v * HID);
    const float4* wr = (const float4*)(Wxw + o * HID);
    float s = Wxb[o];
#pragma unroll
    for (int i = 0; i < 4; i++) {
        float4 e = __ldg(&er[i]);
        float4 w = __ldg(&wr[i]);
        s += e.x * w.x + e.y * w.y + e.z * w.z + e.w * w.w;
    }
    g_xtab[tid] = s;
}

// ---------------------------------------------------------------------------
// Kernel 2: recurrence. 1 warp = 8 batch elements; lane = (p, bl):
//   bl = lane & 7 selects batch, p = lane >> 3 owns h[4p..4p+3].
// h exchanged via shuffles (warp-synchronous, no barriers).
// seq rows staged in SMEM; xtab gathers prefetched 2 steps ahead.
// ---------------------------------------------------------------------------
__global__ void __launch_bounds__(32) rnn_scan(const int* __restrict__ seq,
                                               const float* __restrict__ Wh) {
    __shared__ int s_seq[8][TT + 4];   // +4 ints pad -> conflict-free rows
    const int lane = threadIdx.x;
    const int warp = blockIdx.x;       // 0..511
    const int bl = lane & 7;
    const int p  = lane >> 3;

    // Stage this warp's 8 seq rows (32KB) into SMEM, vectorized.
    {
        const int4* sv = (const int4*)seq;
        const int base = warp * 8;
#pragma unroll 4
        for (int i = lane; i < 8 * (TT / 4); i += 32) {
            int row = i >> 8;              // TT/4 == 256
            int col = i & 255;
            int4 d = __ldg(&sv[(base + row) * (TT / 4) + col]);
            *(int4*)&s_seq[row][col * 4] = d;
        }
    }
    __syncwarp();

    // Wh rows for my 4 outputs, packed as f32x2 pairs along h
    float2 wh[4][8];
#pragma unroll
    for (int i = 0; i < 4; i++) {
        const float4* r = (const float4*)(Wh + (4 * p + i) * HID);
#pragma unroll
        for (int j = 0; j < 4; j++) {
            float4 t = __ldg(&r[j]);
            wh[i][2 * j]     = make_float2(t.x, t.y);
            wh[i][2 * j + 1] = make_float2(t.z, t.w);
        }
    }

    float h0 = 0.f, h1 = 0.f, h2 = 0.f, h3 = 0.f;

    const float4* xt = (const float4*)g_xtab;   // [v][p] float4 view
    float4 xp0 = __ldg(&xt[s_seq[bl][0] * 4 + p]);
    float4 xp1 = __ldg(&xt[s_seq[bl][1] * 4 + p]);

#pragma unroll 2
    for (int t = 0; t < TT; t++) {
        // depth-2 prefetch of next x-projection (clamped at tail)
        int tn = (t + 2 < TT) ? (t + 2) : (TT - 1);
        float4 xpn = __ldg(&xt[s_seq[bl][tn] * 4 + p]);

        // gather the full h[16] of my batch as 8 f32x2 pairs via shuffles
        float2 hp[8];
#pragma unroll
        for (int r = 0; r < 4; r++) {
            int src = r * 8 + bl;
            float a0 = __shfl_sync(0xffffffffu, h0, src);
            float a1 = __shfl_sync(0xffffffffu, h1, src);
            float a2 = __shfl_sync(0xffffffffu, h2, src);
            float a3 = __shfl_sync(0xffffffffu, h3, src);
            hp[2 * r]     = make_float2(a0, a1);
            hp[2 * r + 1] = make_float2(a2, a3);
        }

        float2 a0 = make_float2(xp0.x, 0.f);
        float2 a1 = make_float2(xp0.y, 0.f);
        float2 a2 = make_float2(xp0.z, 0.f);
        float2 a3 = make_float2(xp0.w, 0.f);
#pragma unroll
        for (int q = 0; q < 8; q++) {
            a0 = ffma2(wh[0][q], hp[q], a0);
            a1 = ffma2(wh[1][q], hp[q], a1);
            a2 = ffma2(wh[2][q], hp[q], a2);
            a3 = ffma2(wh[3][q], hp[q], a3);
        }
        h0 = tanh_fast(a0.x + a0.y);
        h1 = tanh_fast(a1.x + a1.y);
        h2 = tanh_fast(a2.x + a2.y);
        h3 = tanh_fast(a3.x + a3.y);

        xp0 = xp1;
        xp1 = xpn;
    }

    int b = warp * 8 + bl;
    *(float4*)(g_hfin + b * HID + 4 * p) = make_float4(h0, h1, h2, h3);
}

// ---------------------------------------------------------------------------
// Kernel 3: out[b][v] = out_b[v] + sum_h hfin[b][h] * out_w[v][h]
// 1000 warps: warp = (vgrp of 128 cols, bgrp of 1024 rows). Lane owns 4
// consecutive v (out_w tile in 64 regs, loaded once). Broadcast h loads,
// depth-2 prefetch; stores are 512B/warp STG.128, fully coalesced.
// ---------------------------------------------------------------------------
__global__ void __launch_bounds__(128) out_proj(const float* __restrict__ outw,
                                                const float* __restrict__ outb,
                                                float* __restrict__ out) {
    int gw   = (blockIdx.x * blockDim.x + threadIdx.x) >> 5;   // 0..999
    int lane = threadIdx.x & 31;
    int vgrp = gw % 250;
    int bgrp = gw / 250;
    int v0 = vgrp * 128 + lane * 4;

    float2 w[4][8];
#pragma unroll
    for (int i = 0; i < 4; i++) {
        const float4* r = (const float4*)(outw + (v0 + i) * HID);
#pragma unroll
        for (int j = 0; j < 4; j++) {
            float4 t = __ldg(&r[j]);
            w[i][2 * j]     = make_float2(t.x, t.y);
            w[i][2 * j + 1] = make_float2(t.z, t.w);
        }
    }
    float4 ob = __ldg((const float4*)(outb + v0));

    const int bcnt = BATCH / 4;
    const int b0 = bgrp * bcnt;
    const float4* hf = (const float4*)g_hfin;

    // depth-2 prefetch buffers (all lanes same address -> broadcast)
    float4 ha0 = __ldg(&hf[(size_t)b0 * 4 + 0]);
    float4 ha1 = __ldg(&hf[(size_t)b0 * 4 + 1]);
    float4 ha2 = __ldg(&hf[(size_t)b0 * 4 + 2]);
    float4 ha3 = __ldg(&hf[(size_t)b0 * 4 + 3]);
    float4 hb0 = __ldg(&hf[(size_t)(b0 + 1) * 4 + 0]);
    float4 hb1 = __ldg(&hf[(size_t)(b0 + 1) * 4 + 1]);
    float4 hb2 = __ldg(&hf[(size_t)(b0 + 1) * 4 + 2]);
    float4 hb3 = __ldg(&hf[(size_t)(b0 + 1) * 4 + 3]);

#pragma unroll 2
    for (int b = b0; b < b0 + bcnt; b++) {
        int bn = (b + 2 < b0 + bcnt) ? (b + 2) : b;
        float4 hn0 = __ldg(&hf[(size_t)bn * 4 + 0]);
        float4 hn1 = __ldg(&hf[(size_t)bn * 4 + 1]);
        float4 hn2 = __ldg(&hf[(size_t)bn * 4 + 2]);
        float4 hn3 = __ldg(&hf[(size_t)bn * 4 + 3]);

        float2 hp[8];
        hp[0] = make_float2(ha0.x, ha0.y); hp[1] = make_float2(ha0.z, ha0.w);
        hp[2] = make_float2(ha1.x, ha1.y); hp[3] = make_float2(ha1.z, ha1.w);
        hp[4] = make_float2(ha2.x, ha2.y); hp[5] = make_float2(ha2.z, ha2.w);
        hp[6] = make_float2(ha3.x, ha3.y); hp[7] = make_float2(ha3.z, ha3.w);

        float2 a0 = make_float2(ob.x, 0.f);
        float2 a1 = make_float2(ob.y, 0.f);
        float2 a2 = make_float2(ob.z, 0.f);
        float2 a3 = make_float2(ob.w, 0.f);
#pragma unroll
        for (int q = 0; q < 8; q++) {
            a0 = ffma2(w[0][q], hp[q], a0);
            a1 = ffma2(w[1][q], hp[q], a1);
            a2 = ffma2(w[2][q], hp[q], a2);
            a3 = ffma2(w[3][q], hp[q], a3);
        }
        float4 res = make_float4(a0.x + a0.y, a1.x + a1.y,
                                 a2.x + a2.y, a3.x + a3.y);
        *(float4*)(out + (size_t)b * NVOC + v0) = res;

        ha0 = hb0; ha1 = hb1; ha2 = hb2; ha3 = hb3;
        hb0 = hn0; hb1 = hn1; hb2 = hn2; hb3 = hn3;
    }
}

// ---------------------------------------------------------------------------
extern "C" void kernel_launch(void* const* d_in, const int* in_sizes, int n_in,
                              void* d_out, int out_size) {
    const int*   seq   = (const int*)d_in[0];
    const float* embed = (const float*)d_in[1];
    const float* Wh    = (const float*)d_in[2];
    const float* Wxw   = (const float*)d_in[3];
    const float* Wxb   = (const float*)d_in[4];
    const float* outw  = (const float*)d_in[5];
    const float* outb  = (const float*)d_in[6];
    float* out = (float*)d_out;

    build_xtab<<<(NVOC * HID + 255) / 256, 256>>>(embed, Wxw, Wxb);
    rnn_scan<<<BATCH / 8, 32>>>(seq, Wh);
    out_proj<<<250, 128>>>(outw, outb, out);
}

// round 3
// speedup vs baseline: 1.1881x; 1.1881x over previous
#include <cuda_runtime.h>
#include <cuda_bf16.h>

#define BATCH 4096
#define TT    1024
#define NVOC  32000
#define HID   16

typedef unsigned long long ull;

// Scratch (device globals: allocation-free rule)
__device__ float g_xtab[NVOC * HID];   // 2MB: precomputed x-projection per token
__device__ float g_hfin[BATCH * HID];  // 256KB: final hidden states

// ---- packed f32x2 helpers on 64-bit registers (no per-op pack/unpack) ----
__device__ __forceinline__ ull ffma2(ull a, ull b, ull c) {
    ull d;
    asm("fma.rn.f32x2 %0, %1, %2, %3;" : "=l"(d) : "l"(a), "l"(b), "l"(c));
    return d;
}
__device__ __forceinline__ ull add2(ull a, ull b) {
    ull d;
    asm("add.rn.f32x2 %0, %1, %2;" : "=l"(d) : "l"(a), "l"(b));
    return d;
}
__device__ __forceinline__ ull pk(float lo, float hi) {
    ull r;
    asm("mov.b64 %0, {%1, %2};" : "=l"(r) : "f"(lo), "f"(hi));
    return r;
}
__device__ __forceinline__ float hsum2(ull a) {   // lo + hi
    float lo, hi;
    asm("mov.b64 {%0, %1}, %2;" : "=f"(lo), "=f"(hi) : "l"(a));
    return lo + hi;
}
// single-MUFU tanh (sm_75+); ~1e-5 abs err, contraction keeps it bounded
__device__ __forceinline__ float tanhx(float x) {
    float r;
    asm("tanh.approx.f32 %0, %1;" : "=f"(r) : "f"(x));
    return r;
}

// ---------------------------------------------------------------------------
// Kernel 1: xtab[v][o] = Wx_b[o] + sum_h embed[v][h] * Wx_w[o][h]
// ---------------------------------------------------------------------------
__global__ void build_xtab(const float* __restrict__ embed,
                           const float* __restrict__ Wxw,
                           const float* __restrict__ Wxb) {
    int tid = blockIdx.x * blockDim.x + threadIdx.x;
    if (tid >= NVOC * HID) return;
    int v = tid >> 4;
    int o = tid & 15;
    const float4* er = (const float4*)(embed + v * HID);
    const float4* wr = (const float4*)(Wxw + o * HID);
    float s = Wxb[o];
#pragma unroll
    for (int i = 0; i < 4; i++) {
        float4 e = __ldg(&er[i]);
        float4 w = __ldg(&wr[i]);
        s += e.x * w.x + e.y * w.y + e.z * w.z + e.w * w.w;
    }
    g_xtab[tid] = s;
}

// ---------------------------------------------------------------------------
// Kernel 2: recurrence. 1 warp = 8 batch elements; lane = (p, bl):
//   bl = lane & 7 selects batch, p = lane >> 3 owns h[4p..4p+3].
// Depth-8 software pipeline on the token-LDS + xtab-LDG chain (~300cyc) so
// no per-step long_scoreboard stall at <1 warp/SMSP occupancy.
// ---------------------------------------------------------------------------
#define PF 8
__global__ void __launch_bounds__(32) rnn_scan(const int* __restrict__ seq,
                                               const float* __restrict__ Wh) {
    __shared__ int s_seq[8][TT + 4];   // +4 ints pad
    const int lane = threadIdx.x;
    const int warp = blockIdx.x;       // 0..511
    const int bl = lane & 7;
    const int p  = lane >> 3;

    // Stage this warp's 8 seq rows (32KB) into SMEM, vectorized.
    {
        const int4* sv = (const int4*)seq;
        const int base = warp * 8;
#pragma unroll 4
        for (int i = lane; i < 8 * (TT / 4); i += 32) {
            int row = i >> 8;              // TT/4 == 256
            int col = i & 255;
            int4 d = __ldg(&sv[(base + row) * (TT / 4) + col]);
            *(int4*)&s_seq[row][col * 4] = d;
        }
    }
    __syncwarp();

    // Wh rows for my 4 outputs, packed f32x2 along h (64 regs, loop-invariant)
    ull wh[4][8];
#pragma unroll
    for (int i = 0; i < 4; i++) {
        const float4* r = (const float4*)(Wh + (4 * p + i) * HID);
#pragma unroll
        for (int j = 0; j < 4; j++) {
            float4 t = __ldg(&r[j]);
            wh[i][2 * j]     = pk(t.x, t.y);
            wh[i][2 * j + 1] = pk(t.z, t.w);
        }
    }

    float h0 = 0.f, h1 = 0.f, h2 = 0.f, h3 = 0.f;

    const float4* xt = (const float4*)g_xtab;   // [v][p] float4 view

    // prime depth-PF pipeline
    float4 xp[PF];
#pragma unroll
    for (int i = 0; i < PF; i++)
        xp[i] = __ldg(&xt[s_seq[bl][i] * 4 + p]);

#pragma unroll 8
    for (int t = 0; t < TT; t++) {
        float4 cur = xp[t & (PF - 1)];
        // refill this slot for step t+PF (clamped at tail)
        int tn = t + PF;
        if (tn > TT - 1) tn = TT - 1;
        int tok = s_seq[bl][tn];
        xp[t & (PF - 1)] = __ldg(&xt[tok * 4 + p]);

        // gather full h[16] of my batch via 16 independent shuffles
        ull hp[8];
#pragma unroll
        for (int r = 0; r < 4; r++) {
            int src = r * 8 + bl;
            float a0 = __shfl_sync(0xffffffffu, h0, src);
            float a1 = __shfl_sync(0xffffffffu, h1, src);
            float a2 = __shfl_sync(0xffffffffu, h2, src);
            float a3 = __shfl_sync(0xffffffffu, h3, src);
            hp[2 * r]     = pk(a0, a1);
            hp[2 * r + 1] = pk(a2, a3);
        }

        // 4 outputs, each as two 4-deep FFMA2 trees (depth 16+4, not 32)
        ull aL0 = ffma2(wh[0][0], hp[0], pk(cur.x, 0.f));
        ull aL1 = ffma2(wh[1][0], hp[0], pk(cur.y, 0.f));
        ull aL2 = ffma2(wh[2][0], hp[0], pk(cur.z, 0.f));
        ull aL3 = ffma2(wh[3][0], hp[0], pk(cur.w, 0.f));
        ull aH0 = ffma2(wh[0][4], hp[4], 0ull);
        ull aH1 = ffma2(wh[1][4], hp[4], 0ull);
        ull aH2 = ffma2(wh[2][4], hp[4], 0ull);
        ull aH3 = ffma2(wh[3][4], hp[4], 0ull);
#pragma unroll
        for (int q = 1; q < 4; q++) {
            aL0 = ffma2(wh[0][q], hp[q], aL0);
            aL1 = ffma2(wh[1][q], hp[q], aL1);
            aL2 = ffma2(wh[2][q], hp[q], aL2);
            aL3 = ffma2(wh[3][q], hp[q], aL3);
            aH0 = ffma2(wh[0][q + 4], hp[q + 4], aH0);
            aH1 = ffma2(wh[1][q + 4], hp[q + 4], aH1);
            aH2 = ffma2(wh[2][q + 4], hp[q + 4], aH2);
            aH3 = ffma2(wh[3][q + 4], hp[q + 4], aH3);
        }
        h0 = tanhx(hsum2(add2(aL0, aH0)));
        h1 = tanhx(hsum2(add2(aL1, aH1)));
        h2 = tanhx(hsum2(add2(aL2, aH2)));
        h3 = tanhx(hsum2(add2(aL3, aH3)));
    }

    int b = warp * 8 + bl;
    *(float4*)(g_hfin + b * HID + 4 * p) = make_float4(h0, h1, h2, h3);
}

// ---------------------------------------------------------------------------
// Kernel 3: out[b][v] = out_b[v] + sum_h hfin[b][h] * out_w[v][h]
// 1000 warps; lane owns 4 consecutive v (out_w tile in regs). DRAM-write bound:
// streaming stores, depth-2 broadcast h prefetch.
// ---------------------------------------------------------------------------
__global__ void __launch_bounds__(128) out_proj(const float* __restrict__ outw,
                                                const float* __restrict__ outb,
                                                float* __restrict__ out) {
    int gw   = (blockIdx.x * blockDim.x + threadIdx.x) >> 5;   // 0..999
    int lane = threadIdx.x & 31;
    int vgrp = gw % 250;
    int bgrp = gw / 250;
    int v0 = vgrp * 128 + lane * 4;

    ull w[4][8];
#pragma unroll
    for (int i = 0; i < 4; i++) {
        const float4* r = (const float4*)(outw + (v0 + i) * HID);
#pragma unroll
        for (int j = 0; j < 4; j++) {
            float4 t = __ldg(&r[j]);
            w[i][2 * j]     = pk(t.x, t.y);
            w[i][2 * j + 1] = pk(t.z, t.w);
        }
    }
    float4 ob = __ldg((const float4*)(outb + v0));

    const int bcnt = BATCH / 4;
    const int b0 = bgrp * bcnt;
    const float4* hf = (const float4*)g_hfin;

    float4 ha0 = __ldg(&hf[(size_t)b0 * 4 + 0]);
    float4 ha1 = __ldg(&hf[(size_t)b0 * 4 + 1]);
    float4 ha2 = __ldg(&hf[(size_t)b0 * 4 + 2]);
    float4 ha3 = __ldg(&hf[(size_t)b0 * 4 + 3]);
    float4 hb0 = __ldg(&hf[(size_t)(b0 + 1) * 4 + 0]);
    float4 hb1 = __ldg(&hf[(size_t)(b0 + 1) * 4 + 1]);
    float4 hb2 = __ldg(&hf[(size_t)(b0 + 1) * 4 + 2]);
    float4 hb3 = __ldg(&hf[(size_t)(b0 + 1) * 4 + 3]);

#pragma unroll 2
    for (int b = b0; b < b0 + bcnt; b++) {
        int bn = (b + 2 < b0 + bcnt) ? (b + 2) : b;
        float4 hn0 = __ldg(&hf[(size_t)bn * 4 + 0]);
        float4 hn1 = __ldg(&hf[(size_t)bn * 4 + 1]);
        float4 hn2 = __ldg(&hf[(size_t)bn * 4 + 2]);
        float4 hn3 = __ldg(&hf[(size_t)bn * 4 + 3]);

        ull hp[8];
        hp[0] = pk(ha0.x, ha0.y); hp[1] = pk(ha0.z, ha0.w);
        hp[2] = pk(ha1.x, ha1.y); hp[3] = pk(ha1.z, ha1.w);
        hp[4] = pk(ha2.x, ha2.y); hp[5] = pk(ha2.z, ha2.w);
        hp[6] = pk(ha3.x, ha3.y); hp[7] = pk(ha3.z, ha3.w);

        ull aL0 = ffma2(w[0][0], hp[0], pk(ob.x, 0.f));
        ull aL1 = ffma2(w[1][0], hp[0], pk(ob.y, 0.f));
        ull aL2 = ffma2(w[2][0], hp[0], pk(ob.z, 0.f));
        ull aL3 = ffma2(w[3][0], hp[0], pk(ob.w, 0.f));
        ull aH0 = ffma2(w[0][4], hp[4], 0ull);
        ull aH1 = ffma2(w[1][4], hp[4], 0ull);
        ull aH2 = ffma2(w[2][4], hp[4], 0ull);
        ull aH3 = ffma2(w[3][4], hp[4], 0ull);
#pragma unroll
        for (int q = 1; q < 4; q++) {
            aL0 = ffma2(w[0][q], hp[q], aL0);
            aL1 = ffma2(w[1][q], hp[q], aL1);
            aL2 = ffma2(w[2][q], hp[q], aL2);
            aL3 = ffma2(w[3][q], hp[q], aL3);
            aH0 = ffma2(w[0][q + 4], hp[q + 4], aH0);
            aH1 = ffma2(w[1][q + 4], hp[q + 4], aH1);
            aH2 = ffma2(w[2][q + 4], hp[q + 4], aH2);
            aH3 = ffma2(w[3][q + 4], hp[q + 4], aH3);
        }
        float4 res = make_float4(hsum2(add2(aL0, aH0)), hsum2(add2(aL1, aH1)),
                                 hsum2(add2(aL2, aH2)), hsum2(add2(aL3, aH3)));
        __stcs((float4*)(out + (size_t)b * NVOC + v0), res);   // streaming: skip L2

        ha0 = hb0; ha1 = hb1; ha2 = hb2; ha3 = hb3;
        hb0 = hn0; hb1 = hn1; hb2 = hn2; hb3 = hn3;
    }
}

// ---------------------------------------------------------------------------
extern "C" void kernel_launch(void* const* d_in, const int* in_sizes, int n_in,
                              void* d_out, int out_size) {
    const int*   seq   = (const int*)d_in[0];
    const float* embed = (const float*)d_in[1];
    const float* Wh    = (const float*)d_in[2];
    const float* Wxw   = (const float*)d_in[3];
    const float* Wxb   = (const float*)d_in[4];
    const float* outw  = (const float*)d_in[5];
    const float* outb  = (const float*)d_in[6];
    float* out = (float*)d_out;

    build_xtab<<<(NVOC * HID + 255) / 256, 256>>>(embed, Wxw, Wxb);
    rnn_scan<<<BATCH / 8, 32>>>(seq, Wh);
    out_proj<<<250, 128>>>(outw, outb, out);
}

// round 4
// speedup vs baseline: 1.2601x; 1.0606x over previous
#include <cuda_runtime.h>
#include <cuda_bf16.h>

#define BATCH 4096
#define TT    1024
#define NVOC  32000
#define HID   16

typedef unsigned long long ull;

// Scratch (device globals: allocation-free rule)
__device__ float g_xtab[NVOC * HID];   // 2MB: precomputed x-projection per token
__device__ float g_hfin[BATCH * HID];  // 256KB: final hidden states

// ---- packed f32x2 helpers on 64-bit registers ----
__device__ __forceinline__ ull ffma2(ull a, ull b, ull c) {
    ull d;
    asm("fma.rn.f32x2 %0, %1, %2, %3;" : "=l"(d) : "l"(a), "l"(b), "l"(c));
    return d;
}
__device__ __forceinline__ ull add2(ull a, ull b) {
    ull d;
    asm("add.rn.f32x2 %0, %1, %2;" : "=l"(d) : "l"(a), "l"(b));
    return d;
}
__device__ __forceinline__ ull pk(float lo, float hi) {
    ull r;
    asm("mov.b64 %0, {%1, %2};" : "=l"(r) : "f"(lo), "f"(hi));
    return r;
}
__device__ __forceinline__ float hsum2(ull a) {   // lo + hi
    float lo, hi;
    asm("mov.b64 {%0, %1}, %2;" : "=f"(lo), "=f"(hi) : "l"(a));
    return lo + hi;
}
__device__ __forceinline__ float tanhx(float x) {
    float r;
    asm("tanh.approx.f32 %0, %1;" : "=f"(r) : "f"(x));
    return r;
}
__device__ __forceinline__ unsigned smem_u32(const void* p) {
    unsigned a;
    asm("{ .reg .u64 t; cvta.to.shared.u64 t, %1; cvt.u32.u64 %0, t; }"
        : "=r"(a) : "l"(p));
    return a;
}

// ---------------------------------------------------------------------------
// Kernel 1: xtab[v][o] = Wx_b[o] + sum_h embed[v][h] * Wx_w[o][h]
// ---------------------------------------------------------------------------
__global__ void build_xtab(const float* __restrict__ embed,
                           const float* __restrict__ Wxw,
                           const float* __restrict__ Wxb) {
    int tid = blockIdx.x * blockDim.x + threadIdx.x;
    if (tid >= NVOC * HID) return;
    int v = tid >> 4;
    int o = tid & 15;
    const float4* er = (const float4*)(embed + v * HID);
    const float4* wr = (const float4*)(Wxw + o * HID);
    float s = Wxb[o];
#pragma unroll
    for (int i = 0; i < 4; i++) {
        float4 e = __ldg(&er[i]);
        float4 w = __ldg(&wr[i]);
        s += e.x * w.x + e.y * w.y + e.z * w.z + e.w * w.w;
    }
    g_xtab[tid] = s;
}

// ---------------------------------------------------------------------------
// Kernel 2: recurrence, shuffle-free.
// 1 warp = 8 batches; lane = (p = lane>>3, bl = lane&7); lane owns h[4p..4p+3]
// of batch bl. h exchanged through a ping-pong SMEM buffer:
//   row stride 20 floats -> STS.128 quarter-warp phases AND LDS.128 phases
//   are bank-conflict-free ({20*bl mod 32} = {0,20,8,28,16,4,24,12}).
// Token ring (LDG, distance 16) feeds xtab ring (LDG, distance 8); no SMEM
// staging of seq (zero reuse).
// ---------------------------------------------------------------------------
__global__ void __launch_bounds__(32) rnn_scan(const int* __restrict__ seq,
                                               const float* __restrict__ Wh) {
    __shared__ float hbuf[2][8 * 20];
    const int lane = threadIdx.x;
    const int warp = blockIdx.x;       // 0..511
    const int bl = lane & 7;
    const int p  = lane >> 3;

    // zero read-buffer 0 (h0 = 0)
    for (int i = lane; i < 8 * 20; i += 32) hbuf[0][i] = 0.f;

    const unsigned sb0 = smem_u32(&hbuf[0][0]) + bl * 80;   // bytes
    const unsigned sb1 = smem_u32(&hbuf[1][0]) + bl * 80;

    // Wh rows for my 4 outputs, packed f32x2 along h (32 ull, loop-invariant)
    ull wh[4][8];
#pragma unroll
    for (int i = 0; i < 4; i++) {
        const float4* r = (const float4*)(Wh + (4 * p + i) * HID);
#pragma unroll
        for (int j = 0; j < 4; j++) {
            float4 t = __ldg(&r[j]);
            wh[i][2 * j]     = pk(t.x, t.y);
            wh[i][2 * j + 1] = pk(t.z, t.w);
        }
    }

    const int* myseq = seq + (warp * 8 + bl) * TT;
    const float4* xt = (const float4*)g_xtab;

    // Prime rings: tokring[i] = token[i+8], xpring[i] = xproj[i]
    int   tokring[8];
    float4 xpring[8];
#pragma unroll
    for (int i = 0; i < 8; i++) {
        tokring[i] = __ldg(&myseq[i + 8]);
        xpring[i]  = __ldg(&xt[__ldg(&myseq[i]) * 4 + p]);
    }
    __syncwarp();

#pragma unroll 8
    for (int t = 0; t < TT; t++) {
        const int slot = t & 7;
        float4 cur = xpring[slot];                 // xproj for step t
        int tok = tokring[slot];                   // token for t+8 (arrived)
        xpring[slot] = __ldg(&xt[tok * 4 + p]);    // xproj for t+8
        int tn = t + 16; if (tn > TT - 1) tn = TT - 1;
        tokring[slot] = __ldg(&myseq[tn]);         // token for t+16

        const unsigned rbase = (t & 1) ? sb1 : sb0;
        const unsigned wbase = (t & 1) ? sb0 : sb1;

        // read full h[16] of my batch: 4x 128-bit LDS, direct 64-bit pairs
        ull hp[8];
        asm volatile("ld.shared.v2.b64 {%0,%1},[%2];"
                     : "=l"(hp[0]), "=l"(hp[1]) : "r"(rbase) : "memory");
        asm volatile("ld.shared.v2.b64 {%0,%1},[%2];"
                     : "=l"(hp[2]), "=l"(hp[3]) : "r"(rbase + 16) : "memory");
        asm volatile("ld.shared.v2.b64 {%0,%1},[%2];"
                     : "=l"(hp[4]), "=l"(hp[5]) : "r"(rbase + 32) : "memory");
        asm volatile("ld.shared.v2.b64 {%0,%1},[%2];"
                     : "=l"(hp[6]), "=l"(hp[7]) : "r"(rbase + 48) : "memory");

        // 4 outputs, each as two 4-deep FFMA2 trees
        ull aL0 = ffma2(wh[0][0], hp[0], pk(cur.x, 0.f));
        ull aL1 = ffma2(wh[1][0], hp[0], pk(cur.y, 0.f));
        ull aL2 = ffma2(wh[2][0], hp[0], pk(cur.z, 0.f));
        ull aL3 = ffma2(wh[3][0], hp[0], pk(cur.w, 0.f));
        ull aH0 = ffma2(wh[0][4], hp[4], 0ull);
        ull aH1 = ffma2(wh[1][4], hp[4], 0ull);
        ull aH2 = ffma2(wh[2][4], hp[4], 0ull);
        ull aH3 = ffma2(wh[3][4], hp[4], 0ull);
#pragma unroll
        for (int q = 1; q < 4; q++) {
            aL0 = ffma2(wh[0][q], hp[q], aL0);
            aL1 = ffma2(wh[1][q], hp[q], aL1);
            aL2 = ffma2(wh[2][q], hp[q], aL2);
            aL3 = ffma2(wh[3][q], hp[q], aL3);
            aH0 = ffma2(wh[0][q + 4], hp[q + 4], aH0);
            aH1 = ffma2(wh[1][q + 4], hp[q + 4], aH1);
            aH2 = ffma2(wh[2][q + 4], hp[q + 4], aH2);
            aH3 = ffma2(wh[3][q + 4], hp[q + 4], aH3);
        }
        float h0 = tanhx(hsum2(add2(aL0, aH0)));
        float h1 = tanhx(hsum2(add2(aL1, aH1)));
        float h2 = tanhx(hsum2(add2(aL2, aH2)));
        float h3 = tanhx(hsum2(add2(aL3, aH3)));

        asm volatile("st.shared.v4.b32 [%0],{%1,%2,%3,%4};"
                     :: "r"(wbase + 16 * p), "f"(h0), "f"(h1), "f"(h2), "f"(h3)
                     : "memory");
        __syncwarp();
    }

    // final h lives in hbuf[TT&1] = hbuf[0]; each lane rereads its own 4
    float4 hf = *(const float4*)&hbuf[0][bl * 20 + 4 * p];
    int b = warp * 8 + bl;
    *(float4*)(g_hfin + b * HID + 4 * p) = hf;
}

// ---------------------------------------------------------------------------
// Kernel 3: out[b][v] = out_b[v] + sum_h hfin[b][h] * out_w[v][h]
// 2000 warps (more store MLP); lane owns 4 consecutive v (weights in regs,
// loaded once). Broadcast h loads depth-2 prefetch; streaming STG.128.
// ---------------------------------------------------------------------------
__global__ void __launch_bounds__(128) out_proj(const float* __restrict__ outw,
                                                const float* __restrict__ outb,
                                                float* __restrict__ out) {
    int gw   = (blockIdx.x * blockDim.x + threadIdx.x) >> 5;   // 0..1999
    int lane = threadIdx.x & 31;
    int vgrp = gw % 250;
    int bgrp = gw / 250;                                       // 0..7
    int v0 = vgrp * 128 + lane * 4;

    ull w[4][8];
#pragma unroll
    for (int i = 0; i < 4; i++) {
        const float4* r = (const float4*)(outw + (v0 + i) * HID);
#pragma unroll
        for (int j = 0; j < 4; j++) {
            float4 t = __ldg(&r[j]);
            w[i][2 * j]     = pk(t.x, t.y);
            w[i][2 * j + 1] = pk(t.z, t.w);
        }
    }
    float4 ob = __ldg((const float4*)(outb + v0));

    const int bcnt = BATCH / 8;                                // 512
    const int b0 = bgrp * bcnt;
    const float4* hf = (const float4*)g_hfin;

    float4 ha0 = __ldg(&hf[(size_t)b0 * 4 + 0]);
    float4 ha1 = __ldg(&hf[(size_t)b0 * 4 + 1]);
    float4 ha2 = __ldg(&hf[(size_t)b0 * 4 + 2]);
    float4 ha3 = __ldg(&hf[(size_t)b0 * 4 + 3]);
    float4 hb0 = __ldg(&hf[(size_t)(b0 + 1) * 4 + 0]);
    float4 hb1 = __ldg(&hf[(size_t)(b0 + 1) * 4 + 1]);
    float4 hb2 = __ldg(&hf[(size_t)(b0 + 1) * 4 + 2]);
    float4 hb3 = __ldg(&hf[(size_t)(b0 + 1) * 4 + 3]);

#pragma unroll 2
    for (int b = b0; b < b0 + bcnt; b++) {
        int bn = (b + 2 < b0 + bcnt) ? (b + 2) : b;
        float4 hn0 = __ldg(&hf[(size_t)bn * 4 + 0]);
        float4 hn1 = __ldg(&hf[(size_t)bn * 4 + 1]);
        float4 hn2 = __ldg(&hf[(size_t)bn * 4 + 2]);
        float4 hn3 = __ldg(&hf[(size_t)bn * 4 + 3]);

        ull hp[8];
        hp[0] = pk(ha0.x, ha0.y); hp[1] = pk(ha0.z, ha0.w);
        hp[2] = pk(ha1.x, ha1.y); hp[3] = pk(ha1.z, ha1.w);
        hp[4] = pk(ha2.x, ha2.y); hp[5] = pk(ha2.z, ha2.w);
        hp[6] = pk(ha3.x, ha3.y); hp[7] = pk(ha3.z, ha3.w);

        ull aL0 = ffma2(w[0][0], hp[0], pk(ob.x, 0.f));
        ull aL1 = ffma2(w[1][0], hp[0], pk(ob.y, 0.f));
        ull aL2 = ffma2(w[2][0], hp[0], pk(ob.z, 0.f));
        ull aL3 = ffma2(w[3][0], hp[0], pk(ob.w, 0.f));
        ull aH0 = ffma2(w[0][4], hp[4], 0ull);
        ull aH1 = ffma2(w[1][4], hp[4], 0ull);
        ull aH2 = ffma2(w[2][4], hp[4], 0ull);
        ull aH3 = ffma2(w[3][4], hp[4], 0ull);
#pragma unroll
        for (int q = 1; q < 4; q++) {
            aL0 = ffma2(w[0][q], hp[q], aL0);
            aL1 = ffma2(w[1][q], hp[q], aL1);
            aL2 = ffma2(w[2][q], hp[q], aL2);
            aL3 = ffma2(w[3][q], hp[q], aL3);
            aH0 = ffma2(w[0][q + 4], hp[q + 4], aH0);
            aH1 = ffma2(w[1][q + 4], hp[q + 4], aH1);
            aH2 = ffma2(w[2][q + 4], hp[q + 4], aH2);
            aH3 = ffma2(w[3][q + 4], hp[q + 4], aH3);
        }
        float4 res = make_float4(hsum2(add2(aL0, aH0)), hsum2(add2(aL1, aH1)),
                                 hsum2(add2(aL2, aH2)), hsum2(add2(aL3, aH3)));
        __stcs((float4*)(out + (size_t)b * NVOC + v0), res);

        ha0 = hb0; ha1 = hb1; ha2 = hb2; ha3 = hb3;
        hb0 = hn0; hb1 = hn1; hb2 = hn2; hb3 = hn3;
    }
}

// ---------------------------------------------------------------------------
extern "C" void kernel_launch(void* const* d_in, const int* in_sizes, int n_in,
                              void* d_out, int out_size) {
    const int*   seq   = (const int*)d_in[0];
    const float* embed = (const float*)d_in[1];
    const float* Wh    = (const float*)d_in[2];
    const float* Wxw   = (const float*)d_in[3];
    const float* Wxb   = (const float*)d_in[4];
    const float* outw  = (const float*)d_in[5];
    const float* outb  = (const float*)d_in[6];
    float* out = (float*)d_out;

    build_xtab<<<(NVOC * HID + 255) / 256, 256>>>(embed, Wxw, Wxb);
    rnn_scan<<<BATCH / 8, 32>>>(seq, Wh);
    out_proj<<<500, 128>>>(outw, outb, out);
}